// round 1
// baseline (speedup 1.0000x reference)
#include <cuda_runtime.h>

#define BATCH   4
#define NPTS    8192
#define TOTAL   (BATCH * NPTS)      // 32768 points per array
#define TPP     8                   // query points per thread (register tile)
#define THREADS 256
#define CHUNK   (TPP * THREADS)     // 2048 query points per block
#define NCHUNK  (NPTS / CHUNK)      // 4
#define SLICE   512                 // candidates per block
#define NSLICE  (NPTS / SLICE)      // 16

// Scratch (no allocation allowed in kernel_launch):
// g_pts[a][b*NPTS + i] = (x, y, z, x^2+y^2+z^2) for array a (0 = p1, 1 = p2)
// g_minbits[dir][...]  = float-as-int running min (positive floats -> int order ok)
__device__ float4   g_pts[2][TOTAL];
__device__ unsigned g_minbits[2][TOTAL];

__global__ void prep_kernel(const float* __restrict__ p1,
                            const float* __restrict__ p2) {
    int i = blockIdx.x * blockDim.x + threadIdx.x;
    if (i >= TOTAL) return;
    float x = p1[3 * i + 0], y = p1[3 * i + 1], z = p1[3 * i + 2];
    g_pts[0][i] = make_float4(x, y, z, fmaf(x, x, fmaf(y, y, z * z)));
    x = p2[3 * i + 0]; y = p2[3 * i + 1]; z = p2[3 * i + 2];
    g_pts[1][i] = make_float4(x, y, z, fmaf(x, x, fmaf(y, y, z * z)));
    g_minbits[0][i] = 0x7f800000u;  // +inf
    g_minbits[1][i] = 0x7f800000u;
}

// grid: (NCHUNK, NSLICE, 2*BATCH); z = (b << 1) | dir
// dir 0: queries = p1, candidates = p2 ; dir 1: swapped.
// dist^2(q, c) = q.n + (c.n - 2*q.c) ; fold -2 into query regs once.
__global__ __launch_bounds__(THREADS) void min_kernel() {
    __shared__ float4 sc[SLICE];

    const int z   = blockIdx.z;
    const int dir = z & 1;
    const int b   = z >> 1;

    const float4* __restrict__ q = g_pts[dir]     + b * NPTS;
    const float4* __restrict__ c = g_pts[dir ^ 1] + b * NPTS + blockIdx.y * SLICE;
    unsigned* mb = g_minbits[dir] + b * NPTS;

    const int tid = threadIdx.x;

    #pragma unroll
    for (int j = 0; j < SLICE / THREADS; j++)
        sc[tid + j * THREADS] = c[tid + j * THREADS];
    __syncthreads();

    const int pbase = blockIdx.x * CHUNK + tid;

    float qx[TPP], qy[TPP], qz[TPP], qn[TPP], mn[TPP];
    #pragma unroll
    for (int i = 0; i < TPP; i++) {
        float4 p = q[pbase + i * THREADS];
        qx[i] = -2.0f * p.x;
        qy[i] = -2.0f * p.y;
        qz[i] = -2.0f * p.z;
        qn[i] = p.w;
        mn[i] = 3.4e38f;
    }

    #pragma unroll 4
    for (int m = 0; m < SLICE; m++) {
        const float4 cc = sc[m];  // warp-uniform broadcast LDS.128
        #pragma unroll
        for (int i = 0; i < TPP; i++) {
            float t = fmaf(qx[i], cc.x, cc.w);
            t       = fmaf(qy[i], cc.y, t);
            t       = fmaf(qz[i], cc.z, t);
            mn[i]   = fminf(mn[i], t);
        }
    }

    #pragma unroll
    for (int i = 0; i < TPP; i++) {
        float v = fmaxf(mn[i] + qn[i], 0.0f);  // clamp: keep int-order atomicMin valid
        atomicMin((int*)&mb[pbase + i * THREADS], __float_as_int(v));
    }
}

__global__ void reduce_kernel(float* __restrict__ out) {
    __shared__ float ssum[32];
    const int tid = threadIdx.x;
    const int* vals = (const int*)g_minbits;

    float s = 0.0f;
    for (int i = tid; i < 2 * TOTAL; i += blockDim.x)
        s += __int_as_float(vals[i]);

    #pragma unroll
    for (int o = 16; o; o >>= 1) s += __shfl_down_sync(0xffffffffu, s, o);
    if ((tid & 31) == 0) ssum[tid >> 5] = s;
    __syncthreads();
    if (tid < 32) {
        s = (tid < (int)(blockDim.x >> 5)) ? ssum[tid] : 0.0f;
        #pragma unroll
        for (int o = 16; o; o >>= 1) s += __shfl_down_sync(0xffffffffu, s, o);
        if (tid == 0) out[0] = s / (float)(BATCH * NPTS);
    }
}

extern "C" void kernel_launch(void* const* d_in, const int* in_sizes, int n_in,
                              void* d_out, int out_size) {
    const float* p1 = (const float*)d_in[0];
    const float* p2 = (const float*)d_in[1];

    prep_kernel<<<(TOTAL + 255) / 256, 256>>>(p1, p2);

    dim3 grid(NCHUNK, NSLICE, 2 * BATCH);
    min_kernel<<<grid, THREADS>>>();

    reduce_kernel<<<1, 1024>>>((float*)d_out);
}